// round 4
// baseline (speedup 1.0000x reference)
#include <cuda_runtime.h>
#include <cuda_bf16.h>

// LandmarksLoss: mean((pred - true)^2) where true[b,l,h,w] =
//   bell[h - round(x_r) + 64, w - round(y_r) + 64] if both indices in [0,128) else 0
// with (y_r, x_r) = true_landmarks[b,l,0], true_landmarks[b,l,1].
//
// Shapes: pred (16,68,224,224) fp32, landmarks (16,68,2) fp32, bell (128,128) fp32.
// Pure HBM-bound streaming reduction (218 MB read). One CTA per (b,l) image,
// float4 loads, deterministic two-stage reduction.

#define H_DIM     224
#define W_DIM     224
#define HW        (H_DIM * W_DIM)      // 50176
#define ROWF4     (W_DIM / 4)          // 56
#define NF4       (HW / 4)             // 12544
#define THREADS   256
#define MAX_BL    4096
#define DELTA     128
#define HALF      64

__device__ float g_partials[MAX_BL];

__global__ void __launch_bounds__(THREADS, 8)
landmarks_stage1(const float* __restrict__ pred,
                 const float* __restrict__ lm,
                 const float* __restrict__ bell)
{
    const int bl = blockIdx.x;
    const float4* img = reinterpret_cast<const float4*>(pred + (size_t)bl * HW);

    // landmarks: [...,0] = y_r, [...,1] = x_r  (round-half-to-even, matches jnp.round)
    const int yr = (int)rintf(__ldg(&lm[2 * bl + 0]));
    const int xr = (int)rintf(__ldg(&lm[2 * bl + 1]));
    const int xoff = HALF - xr;   // ix = h + xoff  (row index into bell)
    const int yoff = HALF - yr;   // iy = w + yoff  (col index into bell)

    float acc = 0.0f;

    #pragma unroll 4
    for (int i = threadIdx.x; i < NF4; i += THREADS) {
        const float4 p = __ldg(&img[i]);

        const int h  = i / ROWF4;
        const int w0 = (i - h * ROWF4) * 4;

        const int ix = h + xoff;
        const bool rowok = ((unsigned)ix < (unsigned)DELTA);
        const int iy0 = w0 + yoff;
        const float* brow = bell + ix * DELTA;

        float t0 = 0.0f, t1 = 0.0f, t2 = 0.0f, t3 = 0.0f;
        if (rowok) {
            if ((unsigned)(iy0 + 0) < (unsigned)DELTA) t0 = __ldg(&brow[iy0 + 0]);
            if ((unsigned)(iy0 + 1) < (unsigned)DELTA) t1 = __ldg(&brow[iy0 + 1]);
            if ((unsigned)(iy0 + 2) < (unsigned)DELTA) t2 = __ldg(&brow[iy0 + 2]);
            if ((unsigned)(iy0 + 3) < (unsigned)DELTA) t3 = __ldg(&brow[iy0 + 3]);
        }

        const float d0 = p.x - t0;
        const float d1 = p.y - t1;
        const float d2 = p.z - t2;
        const float d3 = p.w - t3;
        acc = fmaf(d0, d0, acc);
        acc = fmaf(d1, d1, acc);
        acc = fmaf(d2, d2, acc);
        acc = fmaf(d3, d3, acc);
    }

    // Block reduction (deterministic): warp shuffle then shared across warps.
    #pragma unroll
    for (int off = 16; off > 0; off >>= 1)
        acc += __shfl_down_sync(0xFFFFFFFFu, acc, off);

    __shared__ float s[THREADS / 32];
    const int lane = threadIdx.x & 31;
    const int wid  = threadIdx.x >> 5;
    if (lane == 0) s[wid] = acc;
    __syncthreads();

    if (wid == 0) {
        float v = (lane < THREADS / 32) ? s[lane] : 0.0f;
        #pragma unroll
        for (int off = 4; off > 0; off >>= 1)
            v += __shfl_down_sync(0xFFFFFFFFu, v, off);
        if (lane == 0) g_partials[bl] = v;
    }
}

__global__ void __launch_bounds__(THREADS)
landmarks_stage2(float* __restrict__ out, int n_bl, float inv_n)
{
    float acc = 0.0f;
    for (int i = threadIdx.x; i < n_bl; i += THREADS)
        acc += g_partials[i];

    #pragma unroll
    for (int off = 16; off > 0; off >>= 1)
        acc += __shfl_down_sync(0xFFFFFFFFu, acc, off);

    __shared__ float s[THREADS / 32];
    const int lane = threadIdx.x & 31;
    const int wid  = threadIdx.x >> 5;
    if (lane == 0) s[wid] = acc;
    __syncthreads();

    if (wid == 0) {
        float v = (lane < THREADS / 32) ? s[lane] : 0.0f;
        #pragma unroll
        for (int off = 4; off > 0; off >>= 1)
            v += __shfl_down_sync(0xFFFFFFFFu, v, off);
        if (lane == 0) out[0] = v * inv_n;
    }
}

extern "C" void kernel_launch(void* const* d_in, const int* in_sizes, int n_in,
                              void* d_out, int out_size)
{
    const float* pred = (const float*)d_in[0];  // (B, L, 224, 224)
    const float* lm   = (const float*)d_in[1];  // (B, L, 2)
    const float* bell = (const float*)d_in[2];  // (128, 128)
    float* out = (float*)d_out;

    const int n_bl = in_sizes[1] / 2;           // B*L = 1088
    const float inv_n = 1.0f / ((float)n_bl * (float)HW);

    landmarks_stage1<<<n_bl, THREADS>>>(pred, lm, bell);
    landmarks_stage2<<<1, THREADS>>>(out, n_bl, inv_n);
}